// round 1
// baseline (speedup 1.0000x reference)
#include <cuda_runtime.h>
#include <cuda_bf16.h>
#include <cstdint>

#define DIM   128
#define NP    8128
#define BATCH 262144
#define NG    8
#define GROUP (NP / NG)          // 1016
#define MCTA  256
#define MTILES (BATCH / MCTA)    // 1024
#define A_STRIDE 68              // u32 per smem A row: 136 bf16 (128 + 8 pad)

// ---------------- scratch (no cudaMalloc allowed) ----------------
__device__ float2 g_cs[NP];
__device__ float  g_parts[NG * DIM * DIM];   // column-major partial products
__device__ float  g_q1[4 * DIM * DIM];
__device__ float  g_q2[2 * DIM * DIM];
__device__ float  g_W[DIM * DIM];            // final W, column-major: W(k,n)=g_W[n*128+k]
__device__ uint4  g_bpack[8 * 16 * 32];      // [kstep][ntile][lane] -> {b0h,b1h,b0l,b1l}

// ---------------- helpers ----------------
__device__ __forceinline__ unsigned pk2(float a, float b) {
    __nv_bfloat162 t = __floats2bfloat162_rn(a, b);  // .x = a (low half)
    return *reinterpret_cast<unsigned*>(&t);
}

__device__ __forceinline__ void mma16816(float* c, const unsigned* a, unsigned b0, unsigned b1) {
    asm("mma.sync.aligned.m16n8k16.row.col.f32.bf16.bf16.f32 "
        "{%0,%1,%2,%3}, {%4,%5,%6,%7}, {%8,%9}, {%0,%1,%2,%3};\n"
        : "+f"(c[0]), "+f"(c[1]), "+f"(c[2]), "+f"(c[3])
        : "r"(a[0]), "r"(a[1]), "r"(a[2]), "r"(a[3]), "r"(b0), "r"(b1));
}

// ---------------- phase 1a: cos/sin precompute ----------------
__global__ void cs_kernel(const float* __restrict__ angles) {
    int p = blockIdx.x * blockDim.x + threadIdx.x;
    if (p < NP) {
        float s, c;
        sincosf(angles[p], &s, &c);
        g_cs[p] = make_float2(c, s);
    }
}

// ---------------- phase 1b: build 8 partial products of the rotation chain ----------------
// Each rotation is right-multiplication by a Givens matrix; group g applies rotations
// [g*GROUP, (g+1)*GROUP) to identity. W = P0*P1*...*P7.
__global__ __launch_bounds__(128) void partials_kernel() {
    extern __shared__ float ws[];   // column-major: ws[c*DIM + r]
    int r  = threadIdx.x;
    int gI = blockIdx.x;
    for (int c = 0; c < DIM; ++c) ws[c * DIM + r] = (c == r) ? 1.f : 0.f;

    int p0 = gI * GROUP, p1 = p0 + GROUP;
    int i = 0, rem = p0;
    while (rem >= DIM - 1 - i) { rem -= DIM - 1 - i; ++i; }
    int j = i + 1 + rem;

    float wi = ws[i * DIM + r];
    #pragma unroll 4
    for (int p = p0; p < p1; ++p) {
        float2 cs = g_cs[p];
        float wj = ws[j * DIM + r];
        float nwi = wi * cs.x + wj * cs.y;
        ws[j * DIM + r] = wj * cs.x - wi * cs.y;
        wi = nwi;
        if (++j == DIM) {
            ws[i * DIM + r] = wi;
            ++i; j = i + 1;
            wi = ws[i * DIM + r];
        }
    }
    ws[i * DIM + r] = wi;
    __syncthreads();
    for (int idx = r; idx < DIM * DIM; idx += 128)
        g_parts[gI * DIM * DIM + idx] = ws[idx];
}

// ---------------- phase 1c: tree combine (C = A*B, all 128x128 col-major) ----------------
__global__ __launch_bounds__(256) void combine_kernel(int level) {
    const float* Pb; float* Cb;
    if (level == 0)      { Pb = g_parts; Cb = g_q1; }
    else if (level == 1) { Pb = g_q1;    Cb = g_q2; }
    else                 { Pb = g_q2;    Cb = g_W;  }
    int pair = blockIdx.y;
    const float* A = Pb + (2 * pair) * DIM * DIM;
    const float* B = Pb + (2 * pair + 1) * DIM * DIM;
    float* C = Cb + pair * DIM * DIM;

    extern __shared__ float sm[];
    float* As = sm;                 // full A, 16384 floats
    float* Bs = sm + DIM * DIM;     // 8 columns of B, 1024 floats

    int tid = threadIdx.x;
    int c0  = blockIdx.x * 8;
    for (int idx = tid; idx < DIM * DIM; idx += 256) As[idx] = A[idx];
    for (int idx = tid; idx < 8 * DIM;  idx += 256) Bs[idx] = B[c0 * DIM + idx];
    __syncthreads();

    int r  = tid & 127;
    int ch = (tid >> 7) * 4;        // 0 or 4
    float acc[4] = {0.f, 0.f, 0.f, 0.f};
    #pragma unroll 4
    for (int k = 0; k < DIM; k += 4) {
        float a0 = As[(k + 0) * DIM + r];
        float a1 = As[(k + 1) * DIM + r];
        float a2 = As[(k + 2) * DIM + r];
        float a3 = As[(k + 3) * DIM + r];
        #pragma unroll
        for (int cc = 0; cc < 4; ++cc) {
            float4 b = *(const float4*)&Bs[(ch + cc) * DIM + k];
            acc[cc] = fmaf(a0, b.x, acc[cc]);
            acc[cc] = fmaf(a1, b.y, acc[cc]);
            acc[cc] = fmaf(a2, b.z, acc[cc]);
            acc[cc] = fmaf(a3, b.w, acc[cc]);
        }
    }
    #pragma unroll
    for (int cc = 0; cc < 4; ++cc)
        C[(c0 + ch + cc) * DIM + r] = acc[cc];
}

// ---------------- phase 1d: split W into bf16 hi/lo, pre-packed per-lane B fragments ----------------
__global__ void split_kernel() {
    int gid = blockIdx.x * 256 + threadIdx.x;   // 4096 = 8 ksteps * 16 ntiles * 32 lanes
    int l = gid & 31, t = (gid >> 5) & 15, s = gid >> 9;
    int g = l >> 2, tg = l & 3;
    int n  = t * 8 + g;
    int k0 = s * 16 + tg * 2;
    const float* Wc = g_W + n * DIM;
    float w00 = Wc[k0], w01 = Wc[k0 + 1], w10 = Wc[k0 + 8], w11 = Wc[k0 + 9];
    float h00 = __bfloat162float(__float2bfloat16_rn(w00));
    float h01 = __bfloat162float(__float2bfloat16_rn(w01));
    float h10 = __bfloat162float(__float2bfloat16_rn(w10));
    float h11 = __bfloat162float(__float2bfloat16_rn(w11));
    uint4 bp;
    bp.x = pk2(w00, w01);
    bp.y = pk2(w10, w11);
    bp.z = pk2(w00 - h00, w01 - h01);
    bp.w = pk2(w10 - h10, w11 - h11);
    g_bpack[gid] = bp;
}

// ---------------- phase 2: GEMM  out = x @ W + bias  (3x bf16 split mma) ----------------
__global__ __launch_bounds__(256, 1) void gemm_kernel(const float4* __restrict__ x4,
                                                      const float* __restrict__ bias,
                                                      float* __restrict__ out) {
    extern __shared__ char smraw[];
    unsigned* Ah = (unsigned*)smraw;                    // 256 x 68 u32
    unsigned* Al = Ah + MCTA * A_STRIDE;
    uint4*    Bp = (uint4*)(Al + MCTA * A_STRIDE);      // 4096 uint4
    float*    bs = (float*)(Bp + 4096);                 // 128 floats

    int tid = threadIdx.x, lane = tid & 31, w = tid >> 5;
    int g = lane >> 2, tg = lane & 3;

    for (int idx = tid; idx < 4096; idx += 256) Bp[idx] = g_bpack[idx];
    if (tid < DIM) bs[tid] = bias[tid];

    // load & split x tile: 256 rows x 128 cols fp32 -> bf16 hi/lo
    size_t base = (size_t)blockIdx.x * (MCTA * 32);
    #pragma unroll 4
    for (int pass = 0; pass < 32; ++pass) {
        int f   = pass * 256 + tid;
        int row = f >> 5, c4 = f & 31;
        float4 v = x4[base + f];
        float hx = __bfloat162float(__float2bfloat16_rn(v.x));
        float hy = __bfloat162float(__float2bfloat16_rn(v.y));
        float hz = __bfloat162float(__float2bfloat16_rn(v.z));
        float hw = __bfloat162float(__float2bfloat16_rn(v.w));
        uint2 hh = make_uint2(pk2(v.x, v.y), pk2(v.z, v.w));
        uint2 ll = make_uint2(pk2(v.x - hx, v.y - hy), pk2(v.z - hz, v.w - hw));
        *(uint2*)&Ah[row * A_STRIDE + c4 * 2] = hh;
        *(uint2*)&Al[row * A_STRIDE + c4 * 2] = ll;
    }
    __syncthreads();

    float acc[2][16][4];
    #pragma unroll
    for (int mt = 0; mt < 2; ++mt)
        #pragma unroll
        for (int t = 0; t < 16; ++t)
            #pragma unroll
            for (int q = 0; q < 4; ++q) acc[mt][t][q] = 0.f;

    int r0 = w * 32 + g;
    #pragma unroll
    for (int s = 0; s < 8; ++s) {
        unsigned ah0[4], al0[4], ah1[4], al1[4];
        int b0i = r0 * A_STRIDE + s * 8 + tg;
        int b1i = b0i + 16 * A_STRIDE;
        ah0[0] = Ah[b0i];                 ah0[1] = Ah[b0i + 8 * A_STRIDE];
        ah0[2] = Ah[b0i + 4];             ah0[3] = Ah[b0i + 8 * A_STRIDE + 4];
        al0[0] = Al[b0i];                 al0[1] = Al[b0i + 8 * A_STRIDE];
        al0[2] = Al[b0i + 4];             al0[3] = Al[b0i + 8 * A_STRIDE + 4];
        ah1[0] = Ah[b1i];                 ah1[1] = Ah[b1i + 8 * A_STRIDE];
        ah1[2] = Ah[b1i + 4];             ah1[3] = Ah[b1i + 8 * A_STRIDE + 4];
        al1[0] = Al[b1i];                 al1[1] = Al[b1i + 8 * A_STRIDE];
        al1[2] = Al[b1i + 4];             al1[3] = Al[b1i + 8 * A_STRIDE + 4];
        #pragma unroll
        for (int t = 0; t < 16; ++t) {
            uint4 b = Bp[(s * 16 + t) * 32 + lane];
            mma16816(acc[0][t], ah0, b.x, b.y);   // hi*hi
            mma16816(acc[0][t], al0, b.x, b.y);   // lo*hi
            mma16816(acc[0][t], ah0, b.z, b.w);   // hi*lo
            mma16816(acc[1][t], ah1, b.x, b.y);
            mma16816(acc[1][t], al1, b.x, b.y);
            mma16816(acc[1][t], ah1, b.z, b.w);
        }
    }

    float2* out2 = (float2*)(out + (size_t)blockIdx.x * MCTA * DIM);
    #pragma unroll
    for (int mt = 0; mt < 2; ++mt) {
        int row = w * 32 + mt * 16 + g;
        #pragma unroll
        for (int t = 0; t < 16; ++t) {
            int col = t * 8 + tg * 2;
            float b0 = bs[col], b1 = bs[col + 1];
            out2[(row * DIM + col) >> 1]       = make_float2(acc[mt][t][0] + b0, acc[mt][t][1] + b1);
            out2[((row + 8) * DIM + col) >> 1] = make_float2(acc[mt][t][2] + b0, acc[mt][t][3] + b1);
        }
    }
}

// ---------------- launcher ----------------
extern "C" void kernel_launch(void* const* d_in, const int* in_sizes, int n_in,
                              void* d_out, int out_size) {
    const float* x      = (const float*)d_in[0];
    const float* angles = (const float*)d_in[1];
    const float* bias   = (const float*)d_in[2];
    float* out = (float*)d_out;

    const int PART_SMEM = DIM * DIM * 4;                       // 65536
    const int COMB_SMEM = (DIM * DIM + 8 * DIM) * 4;           // 69632
    const int GEMM_SMEM = 2 * MCTA * A_STRIDE * 4 + 4096 * 16 + DIM * 4;  // 205312

    cudaFuncSetAttribute(partials_kernel, cudaFuncAttributeMaxDynamicSharedMemorySize, PART_SMEM);
    cudaFuncSetAttribute(combine_kernel,  cudaFuncAttributeMaxDynamicSharedMemorySize, COMB_SMEM);
    cudaFuncSetAttribute(gemm_kernel,     cudaFuncAttributeMaxDynamicSharedMemorySize, GEMM_SMEM);

    cs_kernel<<<(NP + 255) / 256, 256>>>(angles);
    partials_kernel<<<NG, 128, PART_SMEM>>>();
    combine_kernel<<<dim3(16, 4), 256, COMB_SMEM>>>(0);
    combine_kernel<<<dim3(16, 2), 256, COMB_SMEM>>>(1);
    combine_kernel<<<dim3(16, 1), 256, COMB_SMEM>>>(2);
    split_kernel<<<16, 256>>>();
    gemm_kernel<<<MTILES, 256, GEMM_SMEM>>>((const float4*)x, bias, out);
}

// round 2
// speedup vs baseline: 1.5055x; 1.5055x over previous
#include <cuda_runtime.h>
#include <cuda_bf16.h>
#include <cstdint>

#define DIM   128
#define NP    8128
#define BATCH 262144
#define NG    8
#define GROUP (NP / NG)          // 1016
#define MCTA  256
#define MTILES (BATCH / MCTA)    // 1024

// ---------------- scratch (no cudaMalloc allowed) ----------------
__device__ float  g_parts[NG * DIM * DIM];   // column-major partial products
__device__ float  g_q1[4 * DIM * DIM];
__device__ float  g_q2[2 * DIM * DIM];
__device__ uint4  g_bpack[8 * 16 * 32];      // [kstep][ntile][lane] -> {b0h,b1h,b0l,b1l}

// ---------------- helpers ----------------
__device__ __forceinline__ unsigned pk2(float a, float b) {
    __nv_bfloat162 t = __floats2bfloat162_rn(a, b);  // .x = a (low half)
    return *reinterpret_cast<unsigned*>(&t);
}

__device__ __forceinline__ void cvt2(float2 v, unsigned& hi, unsigned& lo) {
    float hx = __bfloat162float(__float2bfloat16_rn(v.x));
    float hy = __bfloat162float(__float2bfloat16_rn(v.y));
    hi = pk2(v.x, v.y);
    lo = pk2(v.x - hx, v.y - hy);
}

__device__ __forceinline__ void mma16816(float* c, const unsigned* a, unsigned b0, unsigned b1) {
    asm("mma.sync.aligned.m16n8k16.row.col.f32.bf16.bf16.f32 "
        "{%0,%1,%2,%3}, {%4,%5,%6,%7}, {%8,%9}, {%0,%1,%2,%3};\n"
        : "+f"(c[0]), "+f"(c[1]), "+f"(c[2]), "+f"(c[3])
        : "r"(a[0]), "r"(a[1]), "r"(a[2]), "r"(a[3]), "r"(b0), "r"(b1));
}

// ---------------- phase 1a: 8 partial products of the rotation chain ----------------
// sincos computed in-kernel into smem; serial chain reads cs from smem (no gmem latency).
__global__ __launch_bounds__(128) void partials_kernel(const float* __restrict__ angles) {
    __shared__ float2 cs[GROUP];
    extern __shared__ float ws[];   // column-major: ws[c*DIM + r], 64KB
    int r  = threadIdx.x;
    int gI = blockIdx.x;

    for (int p = r; p < GROUP; p += 128) {
        float s, c;
        sincosf(angles[gI * GROUP + p], &s, &c);
        cs[p] = make_float2(c, s);
    }
    for (int c = 0; c < DIM; ++c) ws[c * DIM + r] = (c == r) ? 1.f : 0.f;
    __syncthreads();

    int p0 = gI * GROUP;
    int i = 0, rem = p0;
    while (rem >= DIM - 1 - i) { rem -= DIM - 1 - i; ++i; }
    int j = i + 1 + rem;

    float wi = ws[i * DIM + r];
    #pragma unroll 4
    for (int p = 0; p < GROUP; ++p) {
        float2 csv = cs[p];
        float wj = ws[j * DIM + r];
        float nwi = wi * csv.x + wj * csv.y;
        ws[j * DIM + r] = wj * csv.x - wi * csv.y;
        wi = nwi;
        if (++j == DIM) {
            ws[i * DIM + r] = wi;
            ++i; j = i + 1;
            wi = ws[i * DIM + r];
        }
    }
    ws[i * DIM + r] = wi;
    __syncthreads();
    for (int idx = r; idx < DIM * DIM; idx += 128)
        g_parts[gI * DIM * DIM + idx] = ws[idx];
}

// ---------------- phase 1b: tree combine (C = A*B, 128x128 col-major) ----------------
// 128 threads/CTA, CTA computes 128 rows x 8 cols. Level 2 also emits g_bpack
// (bf16 hi/lo pre-packed per-lane B fragments) directly from smem — no split kernel.
__global__ __launch_bounds__(128) void combine_kernel(int level) {
    const float* Pb; float* Cb;
    if (level == 0)      { Pb = g_parts; Cb = g_q1; }
    else if (level == 1) { Pb = g_q1;    Cb = g_q2; }
    else                 { Pb = g_q2;    Cb = nullptr; }
    int pair = blockIdx.y;
    const float* A = Pb + (2 * pair) * DIM * DIM;
    const float* B = Pb + (2 * pair + 1) * DIM * DIM;

    extern __shared__ float sm[];
    float* As = sm;                  // 16384 floats (full A)
    float* Bs = sm + DIM * DIM;      // 1024 floats (8 cols of B)
    float* Cs = Bs + 8 * DIM;        // 1024 floats (level-2 staging)

    int tid = threadIdx.x;
    int c0  = blockIdx.x * 8;

    const float4* A4  = (const float4*)A;
    float4*       As4 = (float4*)As;
    #pragma unroll 8
    for (int i = tid; i < DIM * DIM / 4; i += 128) As4[i] = A4[i];
    const float4* B4  = (const float4*)(B + c0 * DIM);
    float4*       Bs4 = (float4*)Bs;
    for (int i = tid; i < 8 * DIM / 4; i += 128) Bs4[i] = B4[i];
    __syncthreads();

    int r = tid;
    float acc[8] = {0.f, 0.f, 0.f, 0.f, 0.f, 0.f, 0.f, 0.f};
    #pragma unroll 8
    for (int k = 0; k < DIM; k += 4) {
        float a0 = As[(k + 0) * DIM + r];
        float a1 = As[(k + 1) * DIM + r];
        float a2 = As[(k + 2) * DIM + r];
        float a3 = As[(k + 3) * DIM + r];
        #pragma unroll
        for (int cc = 0; cc < 8; ++cc) {
            float4 b = Bs4[(cc * DIM + k) >> 2];
            acc[cc] = fmaf(a0, b.x, acc[cc]);
            acc[cc] = fmaf(a1, b.y, acc[cc]);
            acc[cc] = fmaf(a2, b.z, acc[cc]);
            acc[cc] = fmaf(a3, b.w, acc[cc]);
        }
    }

    if (level < 2) {
        float* C = Cb + pair * DIM * DIM;
        #pragma unroll
        for (int cc = 0; cc < 8; ++cc)
            C[(c0 + cc) * DIM + r] = acc[cc];
    } else {
        #pragma unroll
        for (int cc = 0; cc < 8; ++cc)
            Cs[cc * DIM + r] = acc[cc];
        __syncthreads();
        // pack: this CTA owns columns n in [8*bx, 8*bx+8)  (t = blockIdx.x)
        for (int e = tid; e < 256; e += 128) {
            int lane = e & 31, s = e >> 5;
            int g2 = lane >> 2, tg2 = lane & 3;
            int k0 = s * 16 + tg2 * 2;
            const float* Wc = Cs + g2 * DIM;
            float w00 = Wc[k0], w01 = Wc[k0 + 1], w10 = Wc[k0 + 8], w11 = Wc[k0 + 9];
            float h00 = __bfloat162float(__float2bfloat16_rn(w00));
            float h01 = __bfloat162float(__float2bfloat16_rn(w01));
            float h10 = __bfloat162float(__float2bfloat16_rn(w10));
            float h11 = __bfloat162float(__float2bfloat16_rn(w11));
            uint4 bp;
            bp.x = pk2(w00, w01);
            bp.y = pk2(w10, w11);
            bp.z = pk2(w00 - h00, w01 - h01);
            bp.w = pk2(w10 - h10, w11 - h11);
            g_bpack[s * 512 + blockIdx.x * 32 + lane] = bp;
        }
    }
}

// ---------------- phase 2: GEMM  out = x @ W + bias  (3x bf16 split mma) ----------------
// A-fragments loaded straight from gmem into registers (sector-perfect float2 loads),
// converted in-register, 1-step software prefetch overlaps DRAM with mma.
__global__ __launch_bounds__(256, 1) void gemm_kernel(const float* __restrict__ x,
                                                      const float* __restrict__ bias,
                                                      float* __restrict__ out) {
    extern __shared__ char smraw[];
    uint4* Bp = (uint4*)smraw;               // 4096 uint4 = 64KB
    float* bs = (float*)(Bp + 4096);         // 128 floats

    int tid = threadIdx.x, lane = tid & 31, w = tid >> 5;
    int g = lane >> 2, tg = lane & 3;

    for (int idx = tid; idx < 4096; idx += 256) Bp[idx] = g_bpack[idx];
    if (tid < DIM) bs[tid] = bias[tid];

    const float* xw = x + ((size_t)blockIdx.x * MCTA + w * 32) * DIM;

    float2 p[8];
#define FETCH(S) { int kk = (S) * 16 + 2 * tg;                       \
    p[0] = *(const float2*)(xw + (g     ) * DIM + kk);               \
    p[1] = *(const float2*)(xw + (g +  8) * DIM + kk);               \
    p[2] = *(const float2*)(xw + (g     ) * DIM + kk + 8);           \
    p[3] = *(const float2*)(xw + (g +  8) * DIM + kk + 8);           \
    p[4] = *(const float2*)(xw + (g + 16) * DIM + kk);               \
    p[5] = *(const float2*)(xw + (g + 24) * DIM + kk);               \
    p[6] = *(const float2*)(xw + (g + 16) * DIM + kk + 8);           \
    p[7] = *(const float2*)(xw + (g + 24) * DIM + kk + 8); }

    FETCH(0);
    __syncthreads();   // B-pack + bias ready

    float acc0[16][4], acc1[16][4];
    #pragma unroll
    for (int t = 0; t < 16; ++t)
        #pragma unroll
        for (int q = 0; q < 4; ++q) { acc0[t][q] = 0.f; acc1[t][q] = 0.f; }

    #pragma unroll
    for (int s = 0; s < 8; ++s) {
        unsigned ah0[4], al0[4], ah1[4], al1[4];
        cvt2(p[0], ah0[0], al0[0]);
        cvt2(p[1], ah0[1], al0[1]);
        cvt2(p[2], ah0[2], al0[2]);
        cvt2(p[3], ah0[3], al0[3]);
        cvt2(p[4], ah1[0], al1[0]);
        cvt2(p[5], ah1[1], al1[1]);
        cvt2(p[6], ah1[2], al1[2]);
        cvt2(p[7], ah1[3], al1[3]);
        if (s < 7) FETCH(s + 1);
        const uint4* Bq = Bp + s * 512 + lane;
        #pragma unroll
        for (int t = 0; t < 16; ++t) {
            uint4 b = Bq[t * 32];
            mma16816(acc0[t], ah0, b.x, b.y);   // hi*hi
            mma16816(acc0[t], al0, b.x, b.y);   // lo*hi
            mma16816(acc0[t], ah0, b.z, b.w);   // hi*lo
            mma16816(acc1[t], ah1, b.x, b.y);
            mma16816(acc1[t], al1, b.x, b.y);
            mma16816(acc1[t], ah1, b.z, b.w);
        }
    }
#undef FETCH

    float* outw = out + ((size_t)blockIdx.x * MCTA + w * 32) * DIM;
    #pragma unroll
    for (int t = 0; t < 16; ++t) {
        int col = t * 8 + tg * 2;
        float b0 = bs[col], b1 = bs[col + 1];
        *(float2*)(outw + (g     ) * DIM + col) = make_float2(acc0[t][0] + b0, acc0[t][1] + b1);
        *(float2*)(outw + (g +  8) * DIM + col) = make_float2(acc0[t][2] + b0, acc0[t][3] + b1);
        *(float2*)(outw + (g + 16) * DIM + col) = make_float2(acc1[t][0] + b0, acc1[t][1] + b1);
        *(float2*)(outw + (g + 24) * DIM + col) = make_float2(acc1[t][2] + b0, acc1[t][3] + b1);
    }
}

// ---------------- launcher ----------------
extern "C" void kernel_launch(void* const* d_in, const int* in_sizes, int n_in,
                              void* d_out, int out_size) {
    const float* x      = (const float*)d_in[0];
    const float* angles = (const float*)d_in[1];
    const float* bias   = (const float*)d_in[2];
    float* out = (float*)d_out;

    const int PART_SMEM = DIM * DIM * 4;                          // 65536 dynamic
    const int COMB_SMEM = (DIM * DIM + 8 * DIM + 8 * DIM) * 4;    // 73728
    const int GEMM_SMEM = 4096 * 16 + DIM * 4;                    // 66048

    cudaFuncSetAttribute(partials_kernel, cudaFuncAttributeMaxDynamicSharedMemorySize, PART_SMEM);
    cudaFuncSetAttribute(combine_kernel,  cudaFuncAttributeMaxDynamicSharedMemorySize, COMB_SMEM);
    cudaFuncSetAttribute(gemm_kernel,     cudaFuncAttributeMaxDynamicSharedMemorySize, GEMM_SMEM);

    partials_kernel<<<NG, 128, PART_SMEM>>>(angles);
    combine_kernel<<<dim3(16, 4), 128, COMB_SMEM>>>(0);
    combine_kernel<<<dim3(16, 2), 128, COMB_SMEM>>>(1);
    combine_kernel<<<dim3(16, 1), 128, COMB_SMEM>>>(2);
    gemm_kernel<<<MTILES, 256, GEMM_SMEM>>>(x, bias, out);
}